// round 15
// baseline (speedup 1.0000x reference)
#include <cuda_runtime.h>
#include <cuda_fp16.h>
#include <cstdint>

// ---------------------------------------------------------------------------
// MinGRU block on GB300 (sm_103a via compute_103 => legacy mma.sync path).
//   x += minGRU(LN1(x));  x += FFN(LN2(x))
// B=4, T=8192, H=512, fp32 I/O.
//
// GEMMs plain fp16 (fp32 accumulate), CTA 128x128, 256 threads, warp tile
// 64x32, 3-stage cp.async, 2 CTA/SM. Preacts [k|hpre] fp16, x2 fp16,
// gates via __expf. Scan kernels: 16-token load batching (MLP). LN kernels:
// 2 rows per 256-thread block.
// ---------------------------------------------------------------------------

#define BDIM 4
#define TDIM 8192
#define HDIM 512
#define MDIM (BDIM * TDIM)
#define MH   (MDIM * HDIM)
#define CHUNK 64
#define NCH  (TDIM / CHUNK)

// scratch (device globals: allocation-free)
__device__ __half g_Ah [MH];                 // LN output / GEMM input (fp16)
__device__ __half g_H1 [MH];                 // FFN hidden (fp16)
__device__ __half g_Wzh[1024 * 512];         // [Wz^T ; Wh^T] (N-major, K contig)
__device__ __half g_W1h[512 * 512];
__device__ __half g_W2h[512 * 512];
__device__ __half g_kh [MDIM * 1024];        // [k | hpre] preacts (fp16)
__device__ __half g_x2 [MH];                 // residual after GRU (fp16)
__device__ float g_bzh[1024];
__device__ float g_Ac [BDIM * NCH * HDIM];
__device__ float g_Bc [BDIM * NCH * HDIM];
__device__ float g_Hc [BDIM * NCH * HDIM];

// ============================ PTX helpers ==================================
__device__ __forceinline__ uint32_t smem_u32(const void* p) {
    uint32_t a;
    asm("{ .reg .u64 t; cvta.to.shared.u64 t, %1; cvt.u32.u64 %0, t; }"
        : "=r"(a) : "l"(p));
    return a;
}
__device__ __forceinline__ void ldsm4(uint32_t& r0, uint32_t& r1,
                                      uint32_t& r2, uint32_t& r3, uint32_t addr) {
    asm volatile("ldmatrix.sync.aligned.m8n8.x4.shared.b16 {%0,%1,%2,%3}, [%4];"
                 : "=r"(r0), "=r"(r1), "=r"(r2), "=r"(r3) : "r"(addr));
}
__device__ __forceinline__ void mma16816(float* d, const uint32_t* a,
                                         uint32_t b0, uint32_t b1) {
    asm volatile(
        "mma.sync.aligned.m16n8k16.row.col.f32.f16.f16.f32 "
        "{%0,%1,%2,%3}, {%4,%5,%6,%7}, {%8,%9}, {%0,%1,%2,%3};"
        : "+f"(d[0]), "+f"(d[1]), "+f"(d[2]), "+f"(d[3])
        : "r"(a[0]), "r"(a[1]), "r"(a[2]), "r"(a[3]), "r"(b0), "r"(b1));
}
#define CP16(dst, src) \
    asm volatile("cp.async.cg.shared.global [%0], [%1], 16;" \
                 :: "r"(dst), "l"(src) : "memory")
#define CP_COMMIT() asm volatile("cp.async.commit_group;" ::: "memory")
#define CP_WAIT2()  asm volatile("cp.async.wait_group 2;"  ::: "memory")

// smem tile rows: 64 fp16 = 128B, XOR swizzle on 16B units
__device__ __forceinline__ uint32_t sw_off(int row, int unit) {
    return (uint32_t)row * 128u + (uint32_t)((unit ^ (row & 7)) << 4);
}

// ============================ GEMM kernel ==================================
// C[M,Ntot] = A[M,512] @ Bt^T + bias ; A fp16, Bt fp16 [Ntot,512] K-contig.
// CTA tile 128x128, 256 threads, warp tile 64x32 (2M x 4N warps).
// EPI: 1 relu->fp16 out, 2 +fp16 residual -> fp32 out, 3 plain fp16 out.
static constexpr int ATILE   = 128 * 128;              // 16KB fp16 tile
static constexpr int STAGE_B = 2 * ATILE;              // A + B = 32KB
static constexpr int NSTAGE  = 3;
static constexpr int SMEM_TOT = NSTAGE * STAGE_B;      // 96KB

template <int EPI>
__global__ __launch_bounds__(256, 2)
void mma_gemm(const __half* __restrict__ Ah,
              const __half* __restrict__ Bh,
              const float* __restrict__ bias, const __half* __restrict__ res,
              float* __restrict__ Cf, __half* __restrict__ Ch,
              int Ntot) {
    extern __shared__ char smem[];
    const int tid = threadIdx.x, wid = tid >> 5, lane = tid & 31;
    const int m0 = blockIdx.y * 128, n0 = blockIdx.x * 128;
    const int wm = (wid & 1) * 64;      // 2 warps down M
    const int wn = (wid >> 1) * 32;     // 4 warps across N
    const uint32_t sbase = smem_u32(smem);

    const __half* Ap = Ah + (size_t)m0 * 512;
    const __half* Bp = Bh + (size_t)n0 * 512;

    float acc[4][4][4];
#pragma unroll
    for (int i = 0; i < 4; i++)
#pragma unroll
        for (int j = 0; j < 4; j++)
#pragma unroll
            for (int l = 0; l < 4; l++) acc[i][j][l] = 0.0f;

#define ISSUE_STAGE(c)                                                        \
    {                                                                         \
        const uint32_t sb0 = sbase + (uint32_t)((c) % NSTAGE) * STAGE_B;      \
        _Pragma("unroll")                                                     \
        for (int s = 0; s < 4; s++) {  /* A/B: 128 rows x 8 units */          \
            int idx = tid + s * 256;                                          \
            int row = idx >> 3, uu = idx & 7;                                 \
            uint32_t off = sw_off(row, uu);                                   \
            size_t gof = (size_t)row * 512 + (c) * 64 + uu * 8;               \
            CP16(sb0 + off,         Ap + gof);                                \
            CP16(sb0 + ATILE + off, Bp + gof);                                \
        }                                                                     \
    }

    ISSUE_STAGE(0); CP_COMMIT();
    ISSUE_STAGE(1); CP_COMMIT();
    ISSUE_STAGE(2); CP_COMMIT();

    const int lrow = lane & 15;
    const int lhalf = lane >> 4;

    for (int c = 0; c < 8; c++) {
        CP_WAIT2();
        __syncthreads();
        const uint32_t sA = sbase + (uint32_t)(c % NSTAGE) * STAGE_B;
        const uint32_t sB = sA + ATILE;
#pragma unroll
        for (int k16 = 0; k16 < 4; k16++) {
            const int unit = k16 * 2 + lhalf;
            uint32_t af[4][4], bf[4][2];
#pragma unroll
            for (int mf = 0; mf < 4; mf++)
                ldsm4(af[mf][0], af[mf][1], af[mf][2], af[mf][3],
                      sA + sw_off(wm + mf * 16 + lrow, unit));
#pragma unroll
            for (int g = 0; g < 2; g++) {
                uint32_t r0, r1, r2, r3;
                ldsm4(r0, r1, r2, r3, sB + sw_off(wn + g * 16 + lrow, unit));
                bf[2 * g][0] = r0; bf[2 * g][1] = r2;
                bf[2 * g + 1][0] = r1; bf[2 * g + 1][1] = r3;
            }
#pragma unroll
            for (int mf = 0; mf < 4; mf++)
#pragma unroll
                for (int nf = 0; nf < 4; nf++)
                    mma16816(acc[mf][nf], af[mf], bf[nf][0], bf[nf][1]);
        }
        __syncthreads();
        if (c + 3 < 8) ISSUE_STAGE(c + 3);
        CP_COMMIT();
    }
#undef ISSUE_STAGE

    // ---------------- epilogue ---------------------------------------------
    const int row0 = m0 + wm + (lane >> 2);
    const int coll = wn + (lane & 3) * 2;
#pragma unroll
    for (int mf = 0; mf < 4; mf++) {
#pragma unroll
        for (int nf = 0; nf < 4; nf++) {
            const int col = n0 + coll + nf * 8;
            const float b0 = bias[col], b1 = bias[col + 1];
            const int rA = row0 + mf * 16;
            const int rB = rA + 8;
            float2 vA = make_float2(acc[mf][nf][0] + b0, acc[mf][nf][1] + b1);
            float2 vB = make_float2(acc[mf][nf][2] + b0, acc[mf][nf][3] + b1);
            if (EPI == 1 || EPI == 3) {
                if (EPI == 1) {
                    vA.x = fmaxf(vA.x, 0.f); vA.y = fmaxf(vA.y, 0.f);
                    vB.x = fmaxf(vB.x, 0.f); vB.y = fmaxf(vB.y, 0.f);
                }
                __half2 hA = __floats2half2_rn(vA.x, vA.y);
                __half2 hB = __floats2half2_rn(vB.x, vB.y);
                *reinterpret_cast<__half2*>(Ch + (size_t)rA * Ntot + col) = hA;
                *reinterpret_cast<__half2*>(Ch + (size_t)rB * Ntot + col) = hB;
            } else {
                if (EPI == 2) {
                    const float2 rA2 = __half22float2(
                        *reinterpret_cast<const __half2*>(res + (size_t)rA * Ntot + col));
                    const float2 rB2 = __half22float2(
                        *reinterpret_cast<const __half2*>(res + (size_t)rB * Ntot + col));
                    vA.x += rA2.x; vA.y += rA2.y;
                    vB.x += rB2.x; vB.y += rB2.y;
                }
                *reinterpret_cast<float2*>(Cf + (size_t)rA * Ntot + col) = vA;
                *reinterpret_cast<float2*>(Cf + (size_t)rB * Ntot + col) = vB;
            }
        }
    }
}

// ======== LayerNorm (fp32 in) -> fp16 ; 2 rows per 256-thread block ========
__global__ void ln_half(const float* __restrict__ x,
                        const float* __restrict__ gw,
                        const float* __restrict__ bw,
                        __half* __restrict__ hi) {
    const int grp = threadIdx.x >> 7;          // 0/1: which row
    const int tid = threadIdx.x & 127;
    const int row = blockIdx.x * 2 + grp;
    const float4* xr = reinterpret_cast<const float4*>(x) + (size_t)row * (HDIM / 4);
    float4 v = xr[tid];
    float s  = v.x + v.y + v.z + v.w;
    float sq = v.x * v.x + v.y * v.y + v.z * v.z + v.w * v.w;
#pragma unroll
    for (int o = 16; o; o >>= 1) {
        s  += __shfl_xor_sync(0xffffffffu, s,  o);
        sq += __shfl_xor_sync(0xffffffffu, sq, o);
    }
    __shared__ float ss[2][4], sqq[2][4];
    int w = tid >> 5, l = tid & 31;
    if (l == 0) { ss[grp][w] = s; sqq[grp][w] = sq; }
    __syncthreads();
    s  = ss[grp][0]  + ss[grp][1]  + ss[grp][2]  + ss[grp][3];
    sq = sqq[grp][0] + sqq[grp][1] + sqq[grp][2] + sqq[grp][3];
    float mu  = s * (1.0f / HDIM);
    float var = sq * (1.0f / HDIM) - mu * mu;
    float inv = rsqrtf(var + 1e-5f);
    float4 g4 = reinterpret_cast<const float4*>(gw)[tid];
    float4 b4 = reinterpret_cast<const float4*>(bw)[tid];
    float4 o4;
    o4.x = (v.x - mu) * inv * g4.x + b4.x;
    o4.y = (v.y - mu) * inv * g4.y + b4.y;
    o4.z = (v.z - mu) * inv * g4.z + b4.z;
    o4.w = (v.w - mu) * inv * g4.w + b4.w;
    __half2 h0 = __floats2half2_rn(o4.x, o4.y);
    __half2 h1 = __floats2half2_rn(o4.z, o4.w);
    uint2 hv = make_uint2(*reinterpret_cast<uint32_t*>(&h0),
                          *reinterpret_cast<uint32_t*>(&h1));
    reinterpret_cast<uint2*>(hi)[(size_t)row * (HDIM / 4) + tid] = hv;
}

// ======== LayerNorm (fp16 in) -> fp16 ; 2 rows per 256-thread block ========
__global__ void ln_half_h(const __half* __restrict__ x,
                          const float* __restrict__ gw,
                          const float* __restrict__ bw,
                          __half* __restrict__ hi) {
    const int grp = threadIdx.x >> 7;
    const int tid = threadIdx.x & 127;
    const int row = blockIdx.x * 2 + grp;
    uint2 raw = reinterpret_cast<const uint2*>(x)[(size_t)row * (HDIM / 4) + tid];
    __half2 x0 = *reinterpret_cast<__half2*>(&raw.x);
    __half2 x1 = *reinterpret_cast<__half2*>(&raw.y);
    float2 f0 = __half22float2(x0);
    float2 f1 = __half22float2(x1);
    float s  = f0.x + f0.y + f1.x + f1.y;
    float sq = f0.x * f0.x + f0.y * f0.y + f1.x * f1.x + f1.y * f1.y;
#pragma unroll
    for (int o = 16; o; o >>= 1) {
        s  += __shfl_xor_sync(0xffffffffu, s,  o);
        sq += __shfl_xor_sync(0xffffffffu, sq, o);
    }
    __shared__ float ss[2][4], sqq[2][4];
    int w = tid >> 5, l = tid & 31;
    if (l == 0) { ss[grp][w] = s; sqq[grp][w] = sq; }
    __syncthreads();
    s  = ss[grp][0]  + ss[grp][1]  + ss[grp][2]  + ss[grp][3];
    sq = sqq[grp][0] + sqq[grp][1] + sqq[grp][2] + sqq[grp][3];
    float mu  = s * (1.0f / HDIM);
    float var = sq * (1.0f / HDIM) - mu * mu;
    float inv = rsqrtf(var + 1e-5f);
    float4 g4 = reinterpret_cast<const float4*>(gw)[tid];
    float4 b4 = reinterpret_cast<const float4*>(bw)[tid];
    float4 o4;
    o4.x = (f0.x - mu) * inv * g4.x + b4.x;
    o4.y = (f0.y - mu) * inv * g4.y + b4.y;
    o4.z = (f1.x - mu) * inv * g4.z + b4.z;
    o4.w = (f1.y - mu) * inv * g4.w + b4.w;
    __half2 h0 = __floats2half2_rn(o4.x, o4.y);
    __half2 h1 = __floats2half2_rn(o4.z, o4.w);
    uint2 hv = make_uint2(*reinterpret_cast<uint32_t*>(&h0),
                          *reinterpret_cast<uint32_t*>(&h1));
    reinterpret_cast<uint2*>(hi)[(size_t)row * (HDIM / 4) + tid] = hv;
}

// =============== all-weights transpose -> fp16 (one launch) ================
__global__ void transpose_half4(const float* __restrict__ Wz,
                                const float* __restrict__ Wh,
                                const float* __restrict__ W1,
                                const float* __restrict__ W2,
                                __half* __restrict__ Wzh,
                                __half* __restrict__ W1h,
                                __half* __restrict__ W2h) {
    __shared__ float tile[32][33];
    const int z = blockIdx.z;
    const float* W = (z == 0) ? Wz : (z == 1) ? Wh : (z == 2) ? W1 : W2;
    __half* hi = (z == 0) ? Wzh : (z == 1) ? Wzh + 512 * 512
                 : (z == 2) ? W1h : W2h;
    int n0 = blockIdx.x * 32, k0 = blockIdx.y * 32;
    tile[threadIdx.y][threadIdx.x] =
        W[(size_t)(k0 + threadIdx.y) * 512 + n0 + threadIdx.x];
    __syncthreads();
    float v = tile[threadIdx.x][threadIdx.y];
    hi[(size_t)(n0 + threadIdx.y) * 512 + k0 + threadIdx.x] = __float2half_rn(v);
}

__global__ void bias_cat(const float* __restrict__ bz, const float* __restrict__ bh,
                         float* __restrict__ o) {
    int i = threadIdx.x + blockIdx.x * blockDim.x;
    o[i] = (i < 512) ? bz[i] : bh[i - 512];
}

// ============================ gate + scan ==================================
// vectorized gate on a channel pair, fast-math MUFU exponentials
__device__ __forceinline__ void gate2(__half2 kh2, __half2 hp2,
                                      float2& a, float2& b) {
    float2 k  = __half22float2(kh2);
    float2 hp = __half22float2(hp2);
    a.x = 1.0f / (1.0f + __expf(k.x));
    a.y = 1.0f / (1.0f + __expf(k.y));
    float zx = 1.0f - a.x;               // sigmoid(k) = 1 - a
    float zy = 1.0f - a.y;
    float gx = (hp.x >= 0.0f) ? (hp.x + 0.5f) : 1.0f / (1.0f + __expf(-hp.x));
    float gy = (hp.y >= 0.0f) ? (hp.y + 0.5f) : 1.0f / (1.0f + __expf(-hp.y));
    b.x = zx * gx; b.y = zy * gy;
}

#define TBATCH 16

__global__ void scan_p1(const __half2* __restrict__ kh,
                        float2* __restrict__ Ac, float2* __restrict__ Bc) {
    int h2 = threadIdx.x;            // 256 channel pairs
    int c = blockIdx.x, bb = blockIdx.y;
    size_t base = ((size_t)(bb * TDIM + c * CHUNK)) * 512 + h2;   // half2 units
    float2 Ap = make_float2(1.f, 1.f), Bv = make_float2(0.f, 0.f);
    for (int t0 = 0; t0 < CHUNK; t0 += TBATCH) {
        __half2 k2[TBATCH], hp2[TBATCH];
#pragma unroll
        for (int j = 0; j < TBATCH; j++) {
            k2[j]  = kh[base + (size_t)(t0 + j) * 512];
            hp2[j] = kh[base + (size_t)(t0 + j) * 512 + 256];
        }
#pragma unroll
        for (int j = 0; j < TBATCH; j++) {
            float2 a, b; gate2(k2[j], hp2[j], a, b);
            Bv.x = fmaf(a.x, Bv.x, b.x); Bv.y = fmaf(a.y, Bv.y, b.y);
            Ap.x *= a.x; Ap.y *= a.y;
        }
    }
    int o = (bb * NCH + c) * 256 + h2;
    Ac[o] = Ap; Bc[o] = Bv;
}

__global__ void scan_p2(const float2* __restrict__ Ac, const float2* __restrict__ Bc,
                        float2* __restrict__ Hc) {
    int h2 = threadIdx.x;            // 256 pairs
    int bb = blockIdx.x;
    float2 hcur = make_float2(0.5f, 0.5f);   // h_0 = g(0)
    for (int c0 = 0; c0 < NCH; c0 += 8) {
        float2 A[8], B[8];
#pragma unroll
        for (int j = 0; j < 8; j++) {
            int o = (bb * NCH + c0 + j) * 256 + h2;
            A[j] = Ac[o]; B[j] = Bc[o];
        }
#pragma unroll
        for (int j = 0; j < 8; j++) {
            int o = (bb * NCH + c0 + j) * 256 + h2;
            Hc[o] = hcur;
            hcur.x = fmaf(A[j].x, hcur.x, B[j].x);
            hcur.y = fmaf(A[j].y, hcur.y, B[j].y);
        }
    }
}

__global__ void scan_p3(const __half2* __restrict__ kh,
                        const float2* __restrict__ Hc,
                        const float2* __restrict__ x, __half2* __restrict__ x2) {
    int h2 = threadIdx.x;
    int c = blockIdx.x, bb = blockIdx.y;
    size_t base = ((size_t)(bb * TDIM + c * CHUNK)) * 512 + h2;   // half2 units
    size_t xb   = ((size_t)(bb * TDIM + c * CHUNK)) * 256 + h2;   // float2 units
    float2 hcur = Hc[(bb * NCH + c) * 256 + h2];
    for (int t0 = 0; t0 < CHUNK; t0 += TBATCH) {
        __half2 k2[TBATCH], hp2[TBATCH];
        float2 xx[TBATCH];
#pragma unroll
        for (int j = 0; j < TBATCH; j++) {
            k2[j]  = kh[base + (size_t)(t0 + j) * 512];
            hp2[j] = kh[base + (size_t)(t0 + j) * 512 + 256];
            xx[j]  = x[xb + (size_t)(t0 + j) * 256];
        }
#pragma unroll
        for (int j = 0; j < TBATCH; j++) {
            float2 a, b; gate2(k2[j], hp2[j], a, b);
            hcur.x = fmaf(a.x, hcur.x, b.x);
            hcur.y = fmaf(a.y, hcur.y, b.y);
            x2[xb + (size_t)(t0 + j) * 256] =
                __floats2half2_rn(xx[j].x + hcur.x, xx[j].y + hcur.y);
        }
    }
}

// ============================== launch =====================================
extern "C" void kernel_launch(void* const* d_in, const int* in_sizes, int n_in,
                              void* d_out, int out_size) {
    const float* x     = (const float*)d_in[0];
    const float* ln1_g = (const float*)d_in[1];
    const float* ln1_b = (const float*)d_in[2];
    const float* Wz    = (const float*)d_in[3];
    const float* bz    = (const float*)d_in[4];
    const float* Wh    = (const float*)d_in[5];
    const float* bh    = (const float*)d_in[6];
    const float* ln2_g = (const float*)d_in[7];
    const float* ln2_b = (const float*)d_in[8];
    const float* W1    = (const float*)d_in[9];
    const float* b1    = (const float*)d_in[10];
    const float* W2    = (const float*)d_in[11];
    const float* b2    = (const float*)d_in[12];
    float* out = (float*)d_out;

    __half *pAh, *pH1, *pWzh, *pW1h, *pW2h, *pKH, *pX2;
    float *pBzh, *pAc, *pBc, *pHc;
    cudaGetSymbolAddress((void**)&pAh,  g_Ah);
    cudaGetSymbolAddress((void**)&pH1,  g_H1);
    cudaGetSymbolAddress((void**)&pWzh, g_Wzh);
    cudaGetSymbolAddress((void**)&pW1h, g_W1h);
    cudaGetSymbolAddress((void**)&pW2h, g_W2h);
    cudaGetSymbolAddress((void**)&pKH,  g_kh);
    cudaGetSymbolAddress((void**)&pX2,  g_x2);
    cudaGetSymbolAddress((void**)&pBzh, g_bzh);
    cudaGetSymbolAddress((void**)&pAc,  g_Ac);
    cudaGetSymbolAddress((void**)&pBc,  g_Bc);
    cudaGetSymbolAddress((void**)&pHc,  g_Hc);

    cudaFuncSetAttribute(mma_gemm<1>, cudaFuncAttributeMaxDynamicSharedMemorySize, SMEM_TOT);
    cudaFuncSetAttribute(mma_gemm<2>, cudaFuncAttributeMaxDynamicSharedMemorySize, SMEM_TOT);
    cudaFuncSetAttribute(mma_gemm<3>, cudaFuncAttributeMaxDynamicSharedMemorySize, SMEM_TOT);

    // weight prep (one launch) + fused bias
    transpose_half4<<<dim3(16, 16, 4), dim3(32, 32)>>>(
        Wz, Wh, W1, W2, pWzh, pW1h, pW2h);
    bias_cat<<<4, 256>>>(bz, bh, pBzh);

    // LN1 -> fp16
    ln_half<<<MDIM / 2, 256>>>(x, ln1_g, ln1_b, pAh);
    // [k | hpre] = LN1(x) @ [Wz | Wh] + [bz | bh]  (stored fp16)
    mma_gemm<3><<<dim3(8, MDIM / 128), 256, SMEM_TOT>>>(
        pAh, pWzh, pBzh, nullptr, nullptr, pKH, 1024);
    // chunked linear scan (gates inline, half2, __expf, 16-token batches)
    scan_p1<<<dim3(NCH, BDIM), 256>>>((const __half2*)pKH, (float2*)pAc, (float2*)pBc);
    scan_p2<<<BDIM, 256>>>((const float2*)pAc, (const float2*)pBc, (float2*)pHc);
    scan_p3<<<dim3(NCH, BDIM), 256>>>((const __half2*)pKH, (const float2*)pHc,
                                      (const float2*)x, (__half2*)pX2);
    // LN2 (fp16 in) -> fp16
    ln_half_h<<<MDIM / 2, 256>>>(pX2, ln2_g, ln2_b, pAh);
    // h1 = relu(LN2 @ W1 + b1) -> fp16
    mma_gemm<1><<<dim3(4, MDIM / 128), 256, SMEM_TOT>>>(
        pAh, pW1h, b1, nullptr, nullptr, pH1, 512);
    // out = x2 + h1 @ W2 + b2   (fp16 residual, fp32 out)
    mma_gemm<2><<<dim3(4, MDIM / 128), 256, SMEM_TOT>>>(
        pH1, pW2h, b2, pX2, out, nullptr, 512);
}

// round 16
// speedup vs baseline: 1.0454x; 1.0454x over previous
#include <cuda_runtime.h>
#include <cuda_fp16.h>
#include <cstdint>

// ---------------------------------------------------------------------------
// MinGRU block on GB300 (sm_103a via compute_103 => legacy mma.sync path).
//   x += minGRU(LN1(x));  x += FFN(LN2(x))
// B=4, T=8192, H=512, fp32 I/O.
//
// GEMMs plain fp16 (fp32 accumulate), CTA 128x128, 256 threads, warp tile
// 64x32, 3-stage cp.async, 2 CTA/SM. Preacts [k|hpre] fp16, x2 fp16,
// gates via __expf. Scan kernels use explicit 8-token load batching (MLP).
// (R14 configuration - measured best; deeper batching and 2-row LN both
// measured slower.)
// ---------------------------------------------------------------------------

#define BDIM 4
#define TDIM 8192
#define HDIM 512
#define MDIM (BDIM * TDIM)
#define MH   (MDIM * HDIM)
#define CHUNK 64
#define NCH  (TDIM / CHUNK)

// scratch (device globals: allocation-free)
__device__ __half g_Ah [MH];                 // LN output / GEMM input (fp16)
__device__ __half g_H1 [MH];                 // FFN hidden (fp16)
__device__ __half g_Wzh[1024 * 512];         // [Wz^T ; Wh^T] (N-major, K contig)
__device__ __half g_W1h[512 * 512];
__device__ __half g_W2h[512 * 512];
__device__ __half g_kh [MDIM * 1024];        // [k | hpre] preacts (fp16)
__device__ __half g_x2 [MH];                 // residual after GRU (fp16)
__device__ float g_bzh[1024];
__device__ float g_Ac [BDIM * NCH * HDIM];
__device__ float g_Bc [BDIM * NCH * HDIM];
__device__ float g_Hc [BDIM * NCH * HDIM];

// ============================ PTX helpers ==================================
__device__ __forceinline__ uint32_t smem_u32(const void* p) {
    uint32_t a;
    asm("{ .reg .u64 t; cvta.to.shared.u64 t, %1; cvt.u32.u64 %0, t; }"
        : "=r"(a) : "l"(p));
    return a;
}
__device__ __forceinline__ void ldsm4(uint32_t& r0, uint32_t& r1,
                                      uint32_t& r2, uint32_t& r3, uint32_t addr) {
    asm volatile("ldmatrix.sync.aligned.m8n8.x4.shared.b16 {%0,%1,%2,%3}, [%4];"
                 : "=r"(r0), "=r"(r1), "=r"(r2), "=r"(r3) : "r"(addr));
}
__device__ __forceinline__ void mma16816(float* d, const uint32_t* a,
                                         uint32_t b0, uint32_t b1) {
    asm volatile(
        "mma.sync.aligned.m16n8k16.row.col.f32.f16.f16.f32 "
        "{%0,%1,%2,%3}, {%4,%5,%6,%7}, {%8,%9}, {%0,%1,%2,%3};"
        : "+f"(d[0]), "+f"(d[1]), "+f"(d[2]), "+f"(d[3])
        : "r"(a[0]), "r"(a[1]), "r"(a[2]), "r"(a[3]), "r"(b0), "r"(b1));
}
#define CP16(dst, src) \
    asm volatile("cp.async.cg.shared.global [%0], [%1], 16;" \
                 :: "r"(dst), "l"(src) : "memory")
#define CP_COMMIT() asm volatile("cp.async.commit_group;" ::: "memory")
#define CP_WAIT2()  asm volatile("cp.async.wait_group 2;"  ::: "memory")

// smem tile rows: 64 fp16 = 128B, XOR swizzle on 16B units
__device__ __forceinline__ uint32_t sw_off(int row, int unit) {
    return (uint32_t)row * 128u + (uint32_t)((unit ^ (row & 7)) << 4);
}

// ============================ GEMM kernel ==================================
// C[M,Ntot] = A[M,512] @ Bt^T + bias ; A fp16, Bt fp16 [Ntot,512] K-contig.
// CTA tile 128x128, 256 threads, warp tile 64x32 (2M x 4N warps).
// EPI: 1 relu->fp16 out, 2 +fp16 residual -> fp32 out, 3 plain fp16 out.
static constexpr int ATILE   = 128 * 128;              // 16KB fp16 tile
static constexpr int STAGE_B = 2 * ATILE;              // A + B = 32KB
static constexpr int NSTAGE  = 3;
static constexpr int SMEM_TOT = NSTAGE * STAGE_B;      // 96KB

template <int EPI>
__global__ __launch_bounds__(256, 2)
void mma_gemm(const __half* __restrict__ Ah,
              const __half* __restrict__ Bh,
              const float* __restrict__ bias, const __half* __restrict__ res,
              float* __restrict__ Cf, __half* __restrict__ Ch,
              int Ntot) {
    extern __shared__ char smem[];
    const int tid = threadIdx.x, wid = tid >> 5, lane = tid & 31;
    const int m0 = blockIdx.y * 128, n0 = blockIdx.x * 128;
    const int wm = (wid & 1) * 64;      // 2 warps down M
    const int wn = (wid >> 1) * 32;     // 4 warps across N
    const uint32_t sbase = smem_u32(smem);

    const __half* Ap = Ah + (size_t)m0 * 512;
    const __half* Bp = Bh + (size_t)n0 * 512;

    float acc[4][4][4];
#pragma unroll
    for (int i = 0; i < 4; i++)
#pragma unroll
        for (int j = 0; j < 4; j++)
#pragma unroll
            for (int l = 0; l < 4; l++) acc[i][j][l] = 0.0f;

#define ISSUE_STAGE(c)                                                        \
    {                                                                         \
        const uint32_t sb0 = sbase + (uint32_t)((c) % NSTAGE) * STAGE_B;      \
        _Pragma("unroll")                                                     \
        for (int s = 0; s < 4; s++) {  /* A/B: 128 rows x 8 units */          \
            int idx = tid + s * 256;                                          \
            int row = idx >> 3, uu = idx & 7;                                 \
            uint32_t off = sw_off(row, uu);                                   \
            size_t gof = (size_t)row * 512 + (c) * 64 + uu * 8;               \
            CP16(sb0 + off,         Ap + gof);                                \
            CP16(sb0 + ATILE + off, Bp + gof);                                \
        }                                                                     \
    }

    ISSUE_STAGE(0); CP_COMMIT();
    ISSUE_STAGE(1); CP_COMMIT();
    ISSUE_STAGE(2); CP_COMMIT();

    const int lrow = lane & 15;
    const int lhalf = lane >> 4;

    for (int c = 0; c < 8; c++) {
        CP_WAIT2();
        __syncthreads();
        const uint32_t sA = sbase + (uint32_t)(c % NSTAGE) * STAGE_B;
        const uint32_t sB = sA + ATILE;
#pragma unroll
        for (int k16 = 0; k16 < 4; k16++) {
            const int unit = k16 * 2 + lhalf;
            uint32_t af[4][4], bf[4][2];
#pragma unroll
            for (int mf = 0; mf < 4; mf++)
                ldsm4(af[mf][0], af[mf][1], af[mf][2], af[mf][3],
                      sA + sw_off(wm + mf * 16 + lrow, unit));
#pragma unroll
            for (int g = 0; g < 2; g++) {
                uint32_t r0, r1, r2, r3;
                ldsm4(r0, r1, r2, r3, sB + sw_off(wn + g * 16 + lrow, unit));
                bf[2 * g][0] = r0; bf[2 * g][1] = r2;
                bf[2 * g + 1][0] = r1; bf[2 * g + 1][1] = r3;
            }
#pragma unroll
            for (int mf = 0; mf < 4; mf++)
#pragma unroll
                for (int nf = 0; nf < 4; nf++)
                    mma16816(acc[mf][nf], af[mf], bf[nf][0], bf[nf][1]);
        }
        __syncthreads();
        if (c + 3 < 8) ISSUE_STAGE(c + 3);
        CP_COMMIT();
    }
#undef ISSUE_STAGE

    // ---------------- epilogue ---------------------------------------------
    const int row0 = m0 + wm + (lane >> 2);
    const int coll = wn + (lane & 3) * 2;
#pragma unroll
    for (int mf = 0; mf < 4; mf++) {
#pragma unroll
        for (int nf = 0; nf < 4; nf++) {
            const int col = n0 + coll + nf * 8;
            const float b0 = bias[col], b1 = bias[col + 1];
            const int rA = row0 + mf * 16;
            const int rB = rA + 8;
            float2 vA = make_float2(acc[mf][nf][0] + b0, acc[mf][nf][1] + b1);
            float2 vB = make_float2(acc[mf][nf][2] + b0, acc[mf][nf][3] + b1);
            if (EPI == 1 || EPI == 3) {
                if (EPI == 1) {
                    vA.x = fmaxf(vA.x, 0.f); vA.y = fmaxf(vA.y, 0.f);
                    vB.x = fmaxf(vB.x, 0.f); vB.y = fmaxf(vB.y, 0.f);
                }
                __half2 hA = __floats2half2_rn(vA.x, vA.y);
                __half2 hB = __floats2half2_rn(vB.x, vB.y);
                *reinterpret_cast<__half2*>(Ch + (size_t)rA * Ntot + col) = hA;
                *reinterpret_cast<__half2*>(Ch + (size_t)rB * Ntot + col) = hB;
            } else {
                if (EPI == 2) {
                    const float2 rA2 = __half22float2(
                        *reinterpret_cast<const __half2*>(res + (size_t)rA * Ntot + col));
                    const float2 rB2 = __half22float2(
                        *reinterpret_cast<const __half2*>(res + (size_t)rB * Ntot + col));
                    vA.x += rA2.x; vA.y += rA2.y;
                    vB.x += rB2.x; vB.y += rB2.y;
                }
                *reinterpret_cast<float2*>(Cf + (size_t)rA * Ntot + col) = vA;
                *reinterpret_cast<float2*>(Cf + (size_t)rB * Ntot + col) = vB;
            }
        }
    }
}

// ===================== LayerNorm (fp32 in) -> fp16 =========================
__global__ void ln_half(const float* __restrict__ x,
                        const float* __restrict__ gw,
                        const float* __restrict__ bw,
                        __half* __restrict__ hi) {
    int row = blockIdx.x;
    int tid = threadIdx.x;
    const float4* xr = reinterpret_cast<const float4*>(x) + (size_t)row * (HDIM / 4);
    float4 v = xr[tid];
    float s  = v.x + v.y + v.z + v.w;
    float sq = v.x * v.x + v.y * v.y + v.z * v.z + v.w * v.w;
#pragma unroll
    for (int o = 16; o; o >>= 1) {
        s  += __shfl_xor_sync(0xffffffffu, s,  o);
        sq += __shfl_xor_sync(0xffffffffu, sq, o);
    }
    __shared__ float ss[4], sqq[4];
    int w = tid >> 5, l = tid & 31;
    if (l == 0) { ss[w] = s; sqq[w] = sq; }
    __syncthreads();
    s  = ss[0]  + ss[1]  + ss[2]  + ss[3];
    sq = sqq[0] + sqq[1] + sqq[2] + sqq[3];
    float mu  = s * (1.0f / HDIM);
    float var = sq * (1.0f / HDIM) - mu * mu;
    float inv = rsqrtf(var + 1e-5f);
    float4 g4 = reinterpret_cast<const float4*>(gw)[tid];
    float4 b4 = reinterpret_cast<const float4*>(bw)[tid];
    float4 o4;
    o4.x = (v.x - mu) * inv * g4.x + b4.x;
    o4.y = (v.y - mu) * inv * g4.y + b4.y;
    o4.z = (v.z - mu) * inv * g4.z + b4.z;
    o4.w = (v.w - mu) * inv * g4.w + b4.w;
    __half2 h0 = __floats2half2_rn(o4.x, o4.y);
    __half2 h1 = __floats2half2_rn(o4.z, o4.w);
    uint2 hv = make_uint2(*reinterpret_cast<uint32_t*>(&h0),
                          *reinterpret_cast<uint32_t*>(&h1));
    reinterpret_cast<uint2*>(hi)[(size_t)row * (HDIM / 4) + tid] = hv;
}

// ===================== LayerNorm (fp16 in) -> fp16 =========================
__global__ void ln_half_h(const __half* __restrict__ x,
                          const float* __restrict__ gw,
                          const float* __restrict__ bw,
                          __half* __restrict__ hi) {
    int row = blockIdx.x;
    int tid = threadIdx.x;
    uint2 raw = reinterpret_cast<const uint2*>(x)[(size_t)row * (HDIM / 4) + tid];
    __half2 x0 = *reinterpret_cast<__half2*>(&raw.x);
    __half2 x1 = *reinterpret_cast<__half2*>(&raw.y);
    float2 f0 = __half22float2(x0);
    float2 f1 = __half22float2(x1);
    float s  = f0.x + f0.y + f1.x + f1.y;
    float sq = f0.x * f0.x + f0.y * f0.y + f1.x * f1.x + f1.y * f1.y;
#pragma unroll
    for (int o = 16; o; o >>= 1) {
        s  += __shfl_xor_sync(0xffffffffu, s,  o);
        sq += __shfl_xor_sync(0xffffffffu, sq, o);
    }
    __shared__ float ss[4], sqq[4];
    int w = tid >> 5, l = tid & 31;
    if (l == 0) { ss[w] = s; sqq[w] = sq; }
    __syncthreads();
    s  = ss[0]  + ss[1]  + ss[2]  + ss[3];
    sq = sqq[0] + sqq[1] + sqq[2] + sqq[3];
    float mu  = s * (1.0f / HDIM);
    float var = sq * (1.0f / HDIM) - mu * mu;
    float inv = rsqrtf(var + 1e-5f);
    float4 g4 = reinterpret_cast<const float4*>(gw)[tid];
    float4 b4 = reinterpret_cast<const float4*>(bw)[tid];
    float4 o4;
    o4.x = (f0.x - mu) * inv * g4.x + b4.x;
    o4.y = (f0.y - mu) * inv * g4.y + b4.y;
    o4.z = (f1.x - mu) * inv * g4.z + b4.z;
    o4.w = (f1.y - mu) * inv * g4.w + b4.w;
    __half2 h0 = __floats2half2_rn(o4.x, o4.y);
    __half2 h1 = __floats2half2_rn(o4.z, o4.w);
    uint2 hv = make_uint2(*reinterpret_cast<uint32_t*>(&h0),
                          *reinterpret_cast<uint32_t*>(&h1));
    reinterpret_cast<uint2*>(hi)[(size_t)row * (HDIM / 4) + tid] = hv;
}

// =============== all-weights transpose -> fp16 (one launch) ================
__global__ void transpose_half4(const float* __restrict__ Wz,
                                const float* __restrict__ Wh,
                                const float* __restrict__ W1,
                                const float* __restrict__ W2,
                                __half* __restrict__ Wzh,
                                __half* __restrict__ W1h,
                                __half* __restrict__ W2h) {
    __shared__ float tile[32][33];
    const int z = blockIdx.z;
    const float* W = (z == 0) ? Wz : (z == 1) ? Wh : (z == 2) ? W1 : W2;
    __half* hi = (z == 0) ? Wzh : (z == 1) ? Wzh + 512 * 512
                 : (z == 2) ? W1h : W2h;
    int n0 = blockIdx.x * 32, k0 = blockIdx.y * 32;
    tile[threadIdx.y][threadIdx.x] =
        W[(size_t)(k0 + threadIdx.y) * 512 + n0 + threadIdx.x];
    __syncthreads();
    float v = tile[threadIdx.x][threadIdx.y];
    hi[(size_t)(n0 + threadIdx.y) * 512 + k0 + threadIdx.x] = __float2half_rn(v);
}

__global__ void bias_cat(const float* __restrict__ bz, const float* __restrict__ bh,
                         float* __restrict__ o) {
    int i = threadIdx.x + blockIdx.x * blockDim.x;
    o[i] = (i < 512) ? bz[i] : bh[i - 512];
}

// ============================ gate + scan ==================================
// vectorized gate on a channel pair, fast-math MUFU exponentials
__device__ __forceinline__ void gate2(__half2 kh2, __half2 hp2,
                                      float2& a, float2& b) {
    float2 k  = __half22float2(kh2);
    float2 hp = __half22float2(hp2);
    a.x = 1.0f / (1.0f + __expf(k.x));
    a.y = 1.0f / (1.0f + __expf(k.y));
    float zx = 1.0f - a.x;               // sigmoid(k) = 1 - a
    float zy = 1.0f - a.y;
    float gx = (hp.x >= 0.0f) ? (hp.x + 0.5f) : 1.0f / (1.0f + __expf(-hp.x));
    float gy = (hp.y >= 0.0f) ? (hp.y + 0.5f) : 1.0f / (1.0f + __expf(-hp.y));
    b.x = zx * gx; b.y = zy * gy;
}

#define TBATCH 8

__global__ void scan_p1(const __half2* __restrict__ kh,
                        float2* __restrict__ Ac, float2* __restrict__ Bc) {
    int h2 = threadIdx.x;            // 256 channel pairs
    int c = blockIdx.x, bb = blockIdx.y;
    size_t base = ((size_t)(bb * TDIM + c * CHUNK)) * 512 + h2;   // half2 units
    float2 Ap = make_float2(1.f, 1.f), Bv = make_float2(0.f, 0.f);
    for (int t0 = 0; t0 < CHUNK; t0 += TBATCH) {
        __half2 k2[TBATCH], hp2[TBATCH];
#pragma unroll
        for (int j = 0; j < TBATCH; j++) {
            k2[j]  = kh[base + (size_t)(t0 + j) * 512];
            hp2[j] = kh[base + (size_t)(t0 + j) * 512 + 256];
        }
#pragma unroll
        for (int j = 0; j < TBATCH; j++) {
            float2 a, b; gate2(k2[j], hp2[j], a, b);
            Bv.x = fmaf(a.x, Bv.x, b.x); Bv.y = fmaf(a.y, Bv.y, b.y);
            Ap.x *= a.x; Ap.y *= a.y;
        }
    }
    int o = (bb * NCH + c) * 256 + h2;
    Ac[o] = Ap; Bc[o] = Bv;
}

__global__ void scan_p2(const float2* __restrict__ Ac, const float2* __restrict__ Bc,
                        float2* __restrict__ Hc) {
    int h2 = threadIdx.x;            // 256 pairs
    int bb = blockIdx.x;
    float2 hcur = make_float2(0.5f, 0.5f);   // h_0 = g(0)
    for (int c0 = 0; c0 < NCH; c0 += TBATCH) {
        float2 A[TBATCH], B[TBATCH];
#pragma unroll
        for (int j = 0; j < TBATCH; j++) {
            int o = (bb * NCH + c0 + j) * 256 + h2;
            A[j] = Ac[o]; B[j] = Bc[o];
        }
#pragma unroll
        for (int j = 0; j < TBATCH; j++) {
            int o = (bb * NCH + c0 + j) * 256 + h2;
            Hc[o] = hcur;
            hcur.x = fmaf(A[j].x, hcur.x, B[j].x);
            hcur.y = fmaf(A[j].y, hcur.y, B[j].y);
        }
    }
}

__global__ void scan_p3(const __half2* __restrict__ kh,
                        const float2* __restrict__ Hc,
                        const float2* __restrict__ x, __half2* __restrict__ x2) {
    int h2 = threadIdx.x;
    int c = blockIdx.x, bb = blockIdx.y;
    size_t base = ((size_t)(bb * TDIM + c * CHUNK)) * 512 + h2;   // half2 units
    size_t xb   = ((size_t)(bb * TDIM + c * CHUNK)) * 256 + h2;   // float2 units
    float2 hcur = Hc[(bb * NCH + c) * 256 + h2];
    for (int t0 = 0; t0 < CHUNK; t0 += TBATCH) {
        __half2 k2[TBATCH], hp2[TBATCH];
        float2 xx[TBATCH];
#pragma unroll
        for (int j = 0; j < TBATCH; j++) {
            k2[j]  = kh[base + (size_t)(t0 + j) * 512];
            hp2[j] = kh[base + (size_t)(t0 + j) * 512 + 256];
            xx[j]  = x[xb + (size_t)(t0 + j) * 256];
        }
#pragma unroll
        for (int j = 0; j < TBATCH; j++) {
            float2 a, b; gate2(k2[j], hp2[j], a, b);
            hcur.x = fmaf(a.x, hcur.x, b.x);
            hcur.y = fmaf(a.y, hcur.y, b.y);
            x2[xb + (size_t)(t0 + j) * 256] =
                __floats2half2_rn(xx[j].x + hcur.x, xx[j].y + hcur.y);
        }
    }
}

// ============================== launch =====================================
extern "C" void kernel_launch(void* const* d_in, const int* in_sizes, int n_in,
                              void* d_out, int out_size) {
    const float* x     = (const float*)d_in[0];
    const float* ln1_g = (const float*)d_in[1];
    const float* ln1_b = (const float*)d_in[2];
    const float* Wz    = (const float*)d_in[3];
    const float* bz    = (const float*)d_in[4];
    const float* Wh    = (const float*)d_in[5];
    const float* bh    = (const float*)d_in[6];
    const float* ln2_g = (const float*)d_in[7];
    const float* ln2_b = (const float*)d_in[8];
    const float* W1    = (const float*)d_in[9];
    const float* b1    = (const float*)d_in[10];
    const float* W2    = (const float*)d_in[11];
    const float* b2    = (const float*)d_in[12];
    float* out = (float*)d_out;

    __half *pAh, *pH1, *pWzh, *pW1h, *pW2h, *pKH, *pX2;
    float *pBzh, *pAc, *pBc, *pHc;
    cudaGetSymbolAddress((void**)&pAh,  g_Ah);
    cudaGetSymbolAddress((void**)&pH1,  g_H1);
    cudaGetSymbolAddress((void**)&pWzh, g_Wzh);
    cudaGetSymbolAddress((void**)&pW1h, g_W1h);
    cudaGetSymbolAddress((void**)&pW2h, g_W2h);
    cudaGetSymbolAddress((void**)&pKH,  g_kh);
    cudaGetSymbolAddress((void**)&pX2,  g_x2);
    cudaGetSymbolAddress((void**)&pBzh, g_bzh);
    cudaGetSymbolAddress((void**)&pAc,  g_Ac);
    cudaGetSymbolAddress((void**)&pBc,  g_Bc);
    cudaGetSymbolAddress((void**)&pHc,  g_Hc);

    cudaFuncSetAttribute(mma_gemm<1>, cudaFuncAttributeMaxDynamicSharedMemorySize, SMEM_TOT);
    cudaFuncSetAttribute(mma_gemm<2>, cudaFuncAttributeMaxDynamicSharedMemorySize, SMEM_TOT);
    cudaFuncSetAttribute(mma_gemm<3>, cudaFuncAttributeMaxDynamicSharedMemorySize, SMEM_TOT);

    // weight prep (one launch) + fused bias
    transpose_half4<<<dim3(16, 16, 4), dim3(32, 32)>>>(
        Wz, Wh, W1, W2, pWzh, pW1h, pW2h);
    bias_cat<<<4, 256>>>(bz, bh, pBzh);

    // LN1 -> fp16
    ln_half<<<MDIM, 128>>>(x, ln1_g, ln1_b, pAh);
    // [k | hpre] = LN1(x) @ [Wz | Wh] + [bz | bh]  (stored fp16)
    mma_gemm<3><<<dim3(8, MDIM / 128), 256, SMEM_TOT>>>(
        pAh, pWzh, pBzh, nullptr, nullptr, pKH, 1024);
    // chunked linear scan (gates inline, half2, __expf, 8-token batches)
    scan_p1<<<dim3(NCH, BDIM), 256>>>((const __half2*)pKH, (float2*)pAc, (float2*)pBc);
    scan_p2<<<BDIM, 256>>>((const float2*)pAc, (const float2*)pBc, (float2*)pHc);
    scan_p3<<<dim3(NCH, BDIM), 256>>>((const __half2*)pKH, (const float2*)pHc,
                                      (const float2*)x, (__half2*)pX2);
    // LN2 (fp16 in) -> fp16
    ln_half_h<<<MDIM, 128>>>(pX2, ln2_g, ln2_b, pAh);
    // h1 = relu(LN2 @ W1 + b1) -> fp16
    mma_gemm<1><<<dim3(4, MDIM / 128), 256, SMEM_TOT>>>(
        pAh, pW1h, b1, nullptr, nullptr, pH1, 512);
    // out = x2 + h1 @ W2 + b2   (fp16 residual, fp32 out)
    mma_gemm<2><<<dim3(4, MDIM / 128), 256, SMEM_TOT>>>(
        pH1, pW2h, b2, pX2, out, nullptr, 512);
}

// round 17
// speedup vs baseline: 1.0908x; 1.0434x over previous
#include <cuda_runtime.h>
#include <cuda_fp16.h>
#include <cstdint>

// ---------------------------------------------------------------------------
// MinGRU block on GB300 (sm_103a via compute_103 => legacy mma.sync path).
//   x += minGRU(LN1(x));  x += FFN(LN2(x))
// B=4, T=8192, H=512, fp32 I/O.
//
// GEMMs plain fp16 (fp32 accumulate), CTA 128x128, 256 threads, warp tile
// 64x32, 3-stage cp.async, 2 CTA/SM. Preacts [k|hpre] fp16, x2 fp16.
// Scan gates: single-exp NaN-safe sigmoid + __fdividef (MUFU RCP), 8-token
// load batching. (R14/R16 structure - measured best.)
// ---------------------------------------------------------------------------

#define BDIM 4
#define TDIM 8192
#define HDIM 512
#define MDIM (BDIM * TDIM)
#define MH   (MDIM * HDIM)
#define CHUNK 64
#define NCH  (TDIM / CHUNK)

// scratch (device globals: allocation-free)
__device__ __half g_Ah [MH];                 // LN output / GEMM input (fp16)
__device__ __half g_H1 [MH];                 // FFN hidden (fp16)
__device__ __half g_Wzh[1024 * 512];         // [Wz^T ; Wh^T] (N-major, K contig)
__device__ __half g_W1h[512 * 512];
__device__ __half g_W2h[512 * 512];
__device__ __half g_kh [MDIM * 1024];        // [k | hpre] preacts (fp16)
__device__ __half g_x2 [MH];                 // residual after GRU (fp16)
__device__ float g_bzh[1024];
__device__ float g_Ac [BDIM * NCH * HDIM];
__device__ float g_Bc [BDIM * NCH * HDIM];
__device__ float g_Hc [BDIM * NCH * HDIM];

// ============================ PTX helpers ==================================
__device__ __forceinline__ uint32_t smem_u32(const void* p) {
    uint32_t a;
    asm("{ .reg .u64 t; cvta.to.shared.u64 t, %1; cvt.u32.u64 %0, t; }"
        : "=r"(a) : "l"(p));
    return a;
}
__device__ __forceinline__ void ldsm4(uint32_t& r0, uint32_t& r1,
                                      uint32_t& r2, uint32_t& r3, uint32_t addr) {
    asm volatile("ldmatrix.sync.aligned.m8n8.x4.shared.b16 {%0,%1,%2,%3}, [%4];"
                 : "=r"(r0), "=r"(r1), "=r"(r2), "=r"(r3) : "r"(addr));
}
__device__ __forceinline__ void mma16816(float* d, const uint32_t* a,
                                         uint32_t b0, uint32_t b1) {
    asm volatile(
        "mma.sync.aligned.m16n8k16.row.col.f32.f16.f16.f32 "
        "{%0,%1,%2,%3}, {%4,%5,%6,%7}, {%8,%9}, {%0,%1,%2,%3};"
        : "+f"(d[0]), "+f"(d[1]), "+f"(d[2]), "+f"(d[3])
        : "r"(a[0]), "r"(a[1]), "r"(a[2]), "r"(a[3]), "r"(b0), "r"(b1));
}
#define CP16(dst, src) \
    asm volatile("cp.async.cg.shared.global [%0], [%1], 16;" \
                 :: "r"(dst), "l"(src) : "memory")
#define CP_COMMIT() asm volatile("cp.async.commit_group;" ::: "memory")
#define CP_WAIT2()  asm volatile("cp.async.wait_group 2;"  ::: "memory")

// smem tile rows: 64 fp16 = 128B, XOR swizzle on 16B units
__device__ __forceinline__ uint32_t sw_off(int row, int unit) {
    return (uint32_t)row * 128u + (uint32_t)((unit ^ (row & 7)) << 4);
}

// ============================ GEMM kernel ==================================
// C[M,Ntot] = A[M,512] @ Bt^T + bias ; A fp16, Bt fp16 [Ntot,512] K-contig.
// CTA tile 128x128, 256 threads, warp tile 64x32 (2M x 4N warps).
// EPI: 1 relu->fp16 out, 2 +fp16 residual -> fp32 out, 3 plain fp16 out.
static constexpr int ATILE   = 128 * 128;              // 16KB fp16 tile
static constexpr int STAGE_B = 2 * ATILE;              // A + B = 32KB
static constexpr int NSTAGE  = 3;
static constexpr int SMEM_TOT = NSTAGE * STAGE_B;      // 96KB

template <int EPI>
__global__ __launch_bounds__(256, 2)
void mma_gemm(const __half* __restrict__ Ah,
              const __half* __restrict__ Bh,
              const float* __restrict__ bias, const __half* __restrict__ res,
              float* __restrict__ Cf, __half* __restrict__ Ch,
              int Ntot) {
    extern __shared__ char smem[];
    const int tid = threadIdx.x, wid = tid >> 5, lane = tid & 31;
    const int m0 = blockIdx.y * 128, n0 = blockIdx.x * 128;
    const int wm = (wid & 1) * 64;      // 2 warps down M
    const int wn = (wid >> 1) * 32;     // 4 warps across N
    const uint32_t sbase = smem_u32(smem);

    const __half* Ap = Ah + (size_t)m0 * 512;
    const __half* Bp = Bh + (size_t)n0 * 512;

    float acc[4][4][4];
#pragma unroll
    for (int i = 0; i < 4; i++)
#pragma unroll
        for (int j = 0; j < 4; j++)
#pragma unroll
            for (int l = 0; l < 4; l++) acc[i][j][l] = 0.0f;

#define ISSUE_STAGE(c)                                                        \
    {                                                                         \
        const uint32_t sb0 = sbase + (uint32_t)((c) % NSTAGE) * STAGE_B;      \
        _Pragma("unroll")                                                     \
        for (int s = 0; s < 4; s++) {  /* A/B: 128 rows x 8 units */          \
            int idx = tid + s * 256;                                          \
            int row = idx >> 3, uu = idx & 7;                                 \
            uint32_t off = sw_off(row, uu);                                   \
            size_t gof = (size_t)row * 512 + (c) * 64 + uu * 8;               \
            CP16(sb0 + off,         Ap + gof);                                \
            CP16(sb0 + ATILE + off, Bp + gof);                                \
        }                                                                     \
    }

    ISSUE_STAGE(0); CP_COMMIT();
    ISSUE_STAGE(1); CP_COMMIT();
    ISSUE_STAGE(2); CP_COMMIT();

    const int lrow = lane & 15;
    const int lhalf = lane >> 4;

    for (int c = 0; c < 8; c++) {
        CP_WAIT2();
        __syncthreads();
        const uint32_t sA = sbase + (uint32_t)(c % NSTAGE) * STAGE_B;
        const uint32_t sB = sA + ATILE;
#pragma unroll
        for (int k16 = 0; k16 < 4; k16++) {
            const int unit = k16 * 2 + lhalf;
            uint32_t af[4][4], bf[4][2];
#pragma unroll
            for (int mf = 0; mf < 4; mf++)
                ldsm4(af[mf][0], af[mf][1], af[mf][2], af[mf][3],
                      sA + sw_off(wm + mf * 16 + lrow, unit));
#pragma unroll
            for (int g = 0; g < 2; g++) {
                uint32_t r0, r1, r2, r3;
                ldsm4(r0, r1, r2, r3, sB + sw_off(wn + g * 16 + lrow, unit));
                bf[2 * g][0] = r0; bf[2 * g][1] = r2;
                bf[2 * g + 1][0] = r1; bf[2 * g + 1][1] = r3;
            }
#pragma unroll
            for (int mf = 0; mf < 4; mf++)
#pragma unroll
                for (int nf = 0; nf < 4; nf++)
                    mma16816(acc[mf][nf], af[mf], bf[nf][0], bf[nf][1]);
        }
        __syncthreads();
        if (c + 3 < 8) ISSUE_STAGE(c + 3);
        CP_COMMIT();
    }
#undef ISSUE_STAGE

    // ---------------- epilogue ---------------------------------------------
    const int row0 = m0 + wm + (lane >> 2);
    const int coll = wn + (lane & 3) * 2;
#pragma unroll
    for (int mf = 0; mf < 4; mf++) {
#pragma unroll
        for (int nf = 0; nf < 4; nf++) {
            const int col = n0 + coll + nf * 8;
            const float b0 = bias[col], b1 = bias[col + 1];
            const int rA = row0 + mf * 16;
            const int rB = rA + 8;
            float2 vA = make_float2(acc[mf][nf][0] + b0, acc[mf][nf][1] + b1);
            float2 vB = make_float2(acc[mf][nf][2] + b0, acc[mf][nf][3] + b1);
            if (EPI == 1 || EPI == 3) {
                if (EPI == 1) {
                    vA.x = fmaxf(vA.x, 0.f); vA.y = fmaxf(vA.y, 0.f);
                    vB.x = fmaxf(vB.x, 0.f); vB.y = fmaxf(vB.y, 0.f);
                }
                __half2 hA = __floats2half2_rn(vA.x, vA.y);
                __half2 hB = __floats2half2_rn(vB.x, vB.y);
                *reinterpret_cast<__half2*>(Ch + (size_t)rA * Ntot + col) = hA;
                *reinterpret_cast<__half2*>(Ch + (size_t)rB * Ntot + col) = hB;
            } else {
                if (EPI == 2) {
                    const float2 rA2 = __half22float2(
                        *reinterpret_cast<const __half2*>(res + (size_t)rA * Ntot + col));
                    const float2 rB2 = __half22float2(
                        *reinterpret_cast<const __half2*>(res + (size_t)rB * Ntot + col));
                    vA.x += rA2.x; vA.y += rA2.y;
                    vB.x += rB2.x; vB.y += rB2.y;
                }
                *reinterpret_cast<float2*>(Cf + (size_t)rA * Ntot + col) = vA;
                *reinterpret_cast<float2*>(Cf + (size_t)rB * Ntot + col) = vB;
            }
        }
    }
}

// ===================== LayerNorm (fp32 in) -> fp16 =========================
__global__ void ln_half(const float* __restrict__ x,
                        const float* __restrict__ gw,
                        const float* __restrict__ bw,
                        __half* __restrict__ hi) {
    int row = blockIdx.x;
    int tid = threadIdx.x;
    const float4* xr = reinterpret_cast<const float4*>(x) + (size_t)row * (HDIM / 4);
    float4 v = xr[tid];
    float s  = v.x + v.y + v.z + v.w;
    float sq = v.x * v.x + v.y * v.y + v.z * v.z + v.w * v.w;
#pragma unroll
    for (int o = 16; o; o >>= 1) {
        s  += __shfl_xor_sync(0xffffffffu, s,  o);
        sq += __shfl_xor_sync(0xffffffffu, sq, o);
    }
    __shared__ float ss[4], sqq[4];
    int w = tid >> 5, l = tid & 31;
    if (l == 0) { ss[w] = s; sqq[w] = sq; }
    __syncthreads();
    s  = ss[0]  + ss[1]  + ss[2]  + ss[3];
    sq = sqq[0] + sqq[1] + sqq[2] + sqq[3];
    float mu  = s * (1.0f / HDIM);
    float var = sq * (1.0f / HDIM) - mu * mu;
    float inv = rsqrtf(var + 1e-5f);
    float4 g4 = reinterpret_cast<const float4*>(gw)[tid];
    float4 b4 = reinterpret_cast<const float4*>(bw)[tid];
    float4 o4;
    o4.x = (v.x - mu) * inv * g4.x + b4.x;
    o4.y = (v.y - mu) * inv * g4.y + b4.y;
    o4.z = (v.z - mu) * inv * g4.z + b4.z;
    o4.w = (v.w - mu) * inv * g4.w + b4.w;
    __half2 h0 = __floats2half2_rn(o4.x, o4.y);
    __half2 h1 = __floats2half2_rn(o4.z, o4.w);
    uint2 hv = make_uint2(*reinterpret_cast<uint32_t*>(&h0),
                          *reinterpret_cast<uint32_t*>(&h1));
    reinterpret_cast<uint2*>(hi)[(size_t)row * (HDIM / 4) + tid] = hv;
}

// ===================== LayerNorm (fp16 in) -> fp16 =========================
__global__ void ln_half_h(const __half* __restrict__ x,
                          const float* __restrict__ gw,
                          const float* __restrict__ bw,
                          __half* __restrict__ hi) {
    int row = blockIdx.x;
    int tid = threadIdx.x;
    uint2 raw = reinterpret_cast<const uint2*>(x)[(size_t)row * (HDIM / 4) + tid];
    __half2 x0 = *reinterpret_cast<__half2*>(&raw.x);
    __half2 x1 = *reinterpret_cast<__half2*>(&raw.y);
    float2 f0 = __half22float2(x0);
    float2 f1 = __half22float2(x1);
    float s  = f0.x + f0.y + f1.x + f1.y;
    float sq = f0.x * f0.x + f0.y * f0.y + f1.x * f1.x + f1.y * f1.y;
#pragma unroll
    for (int o = 16; o; o >>= 1) {
        s  += __shfl_xor_sync(0xffffffffu, s,  o);
        sq += __shfl_xor_sync(0xffffffffu, sq, o);
    }
    __shared__ float ss[4], sqq[4];
    int w = tid >> 5, l = tid & 31;
    if (l == 0) { ss[w] = s; sqq[w] = sq; }
    __syncthreads();
    s  = ss[0]  + ss[1]  + ss[2]  + ss[3];
    sq = sqq[0] + sqq[1] + sqq[2] + sqq[3];
    float mu  = s * (1.0f / HDIM);
    float var = sq * (1.0f / HDIM) - mu * mu;
    float inv = rsqrtf(var + 1e-5f);
    float4 g4 = reinterpret_cast<const float4*>(gw)[tid];
    float4 b4 = reinterpret_cast<const float4*>(bw)[tid];
    float4 o4;
    o4.x = (f0.x - mu) * inv * g4.x + b4.x;
    o4.y = (f0.y - mu) * inv * g4.y + b4.y;
    o4.z = (f1.x - mu) * inv * g4.z + b4.z;
    o4.w = (f1.y - mu) * inv * g4.w + b4.w;
    __half2 h0 = __floats2half2_rn(o4.x, o4.y);
    __half2 h1 = __floats2half2_rn(o4.z, o4.w);
    uint2 hv = make_uint2(*reinterpret_cast<uint32_t*>(&h0),
                          *reinterpret_cast<uint32_t*>(&h1));
    reinterpret_cast<uint2*>(hi)[(size_t)row * (HDIM / 4) + tid] = hv;
}

// =============== all-weights transpose -> fp16 (one launch) ================
__global__ void transpose_half4(const float* __restrict__ Wz,
                                const float* __restrict__ Wh,
                                const float* __restrict__ W1,
                                const float* __restrict__ W2,
                                __half* __restrict__ Wzh,
                                __half* __restrict__ W1h,
                                __half* __restrict__ W2h) {
    __shared__ float tile[32][33];
    const int z = blockIdx.z;
    const float* W = (z == 0) ? Wz : (z == 1) ? Wh : (z == 2) ? W1 : W2;
    __half* hi = (z == 0) ? Wzh : (z == 1) ? Wzh + 512 * 512
                 : (z == 2) ? W1h : W2h;
    int n0 = blockIdx.x * 32, k0 = blockIdx.y * 32;
    tile[threadIdx.y][threadIdx.x] =
        W[(size_t)(k0 + threadIdx.y) * 512 + n0 + threadIdx.x];
    __syncthreads();
    float v = tile[threadIdx.x][threadIdx.y];
    hi[(size_t)(n0 + threadIdx.y) * 512 + k0 + threadIdx.x] = __float2half_rn(v);
}

__global__ void bias_cat(const float* __restrict__ bz, const float* __restrict__ bh,
                         float* __restrict__ o) {
    int i = threadIdx.x + blockIdx.x * blockDim.x;
    o[i] = (i < 512) ? bz[i] : bh[i - 512];
}

// ============================ gate + scan ==================================
// single-exp NaN-safe sigmoid pair: a = sigmoid(-k), z = sigmoid(k)
__device__ __forceinline__ void sig_pair(float k, float& a, float& z) {
    float e  = __expf(-fabsf(k));            // in (0,1], never overflows
    float r  = __fdividef(1.0f, 1.0f + e);   // sigmoid(|k|)
    float er = e * r;                        // sigmoid(-|k|)
    a = (k >= 0.0f) ? er : r;                // sigmoid(-k)
    z = (k >= 0.0f) ? r  : er;               // sigmoid(k)
}
// g(x) = x + 0.5 (x>=0) else sigmoid(x)
__device__ __forceinline__ float g_fn(float hp) {
    if (hp >= 0.0f) return hp + 0.5f;
    float e = __expf(hp);                    // hp<0: e in (0,1)
    return __fdividef(e, 1.0f + e);          // sigmoid(hp)
}
__device__ __forceinline__ void gate2(__half2 kh2, __half2 hp2,
                                      float2& a, float2& b) {
    float2 k  = __half22float2(kh2);
    float2 hp = __half22float2(hp2);
    float zx, zy;
    sig_pair(k.x, a.x, zx);
    sig_pair(k.y, a.y, zy);
    b.x = zx * g_fn(hp.x);
    b.y = zy * g_fn(hp.y);
}

#define TBATCH 8

__global__ void scan_p1(const __half2* __restrict__ kh,
                        float2* __restrict__ Ac, float2* __restrict__ Bc) {
    int h2 = threadIdx.x;            // 256 channel pairs
    int c = blockIdx.x, bb = blockIdx.y;
    size_t base = ((size_t)(bb * TDIM + c * CHUNK)) * 512 + h2;   // half2 units
    float2 Ap = make_float2(1.f, 1.f), Bv = make_float2(0.f, 0.f);
    for (int t0 = 0; t0 < CHUNK; t0 += TBATCH) {
        __half2 k2[TBATCH], hp2[TBATCH];
#pragma unroll
        for (int j = 0; j < TBATCH; j++) {
            k2[j]  = kh[base + (size_t)(t0 + j) * 512];
            hp2[j] = kh[base + (size_t)(t0 + j) * 512 + 256];
        }
#pragma unroll
        for (int j = 0; j < TBATCH; j++) {
            float2 a, b; gate2(k2[j], hp2[j], a, b);
            Bv.x = fmaf(a.x, Bv.x, b.x); Bv.y = fmaf(a.y, Bv.y, b.y);
            Ap.x *= a.x; Ap.y *= a.y;
        }
    }
    int o = (bb * NCH + c) * 256 + h2;
    Ac[o] = Ap; Bc[o] = Bv;
}

__global__ void scan_p2(const float2* __restrict__ Ac, const float2* __restrict__ Bc,
                        float2* __restrict__ Hc) {
    int h2 = threadIdx.x;            // 256 pairs
    int bb = blockIdx.x;
    float2 hcur = make_float2(0.5f, 0.5f);   // h_0 = g(0)
    for (int c0 = 0; c0 < NCH; c0 += TBATCH) {
        float2 A[TBATCH], B[TBATCH];
#pragma unroll
        for (int j = 0; j < TBATCH; j++) {
            int o = (bb * NCH + c0 + j) * 256 + h2;
            A[j] = Ac[o]; B[j] = Bc[o];
        }
#pragma unroll
        for (int j = 0; j < TBATCH; j++) {
            int o = (bb * NCH + c0 + j) * 256 + h2;
            Hc[o] = hcur;
            hcur.x = fmaf(A[j].x, hcur.x, B[j].x);
            hcur.y = fmaf(A[j].y, hcur.y, B[j].y);
        }
    }
}

__global__ void scan_p3(const __half2* __restrict__ kh,
                        const float2* __restrict__ Hc,
                        const float2* __restrict__ x, __half2* __restrict__ x2) {
    int h2 = threadIdx.x;
    int c = blockIdx.x, bb = blockIdx.y;
    size_t base = ((size_t)(bb * TDIM + c * CHUNK)) * 512 + h2;   // half2 units
    size_t xb   = ((size_t)(bb * TDIM + c * CHUNK)) * 256 + h2;   // float2 units
    float2 hcur = Hc[(bb * NCH + c) * 256 + h2];
    for (int t0 = 0; t0 < CHUNK; t0 += TBATCH) {
        __half2 k2[TBATCH], hp2[TBATCH];
        float2 xx[TBATCH];
#pragma unroll
        for (int j = 0; j < TBATCH; j++) {
            k2[j]  = kh[base + (size_t)(t0 + j) * 512];
            hp2[j] = kh[base + (size_t)(t0 + j) * 512 + 256];
            xx[j]  = x[xb + (size_t)(t0 + j) * 256];
        }
#pragma unroll
        for (int j = 0; j < TBATCH; j++) {
            float2 a, b; gate2(k2[j], hp2[j], a, b);
            hcur.x = fmaf(a.x, hcur.x, b.x);
            hcur.y = fmaf(a.y, hcur.y, b.y);
            x2[xb + (size_t)(t0 + j) * 256] =
                __floats2half2_rn(xx[j].x + hcur.x, xx[j].y + hcur.y);
        }
    }
}

// ============================== launch =====================================
extern "C" void kernel_launch(void* const* d_in, const int* in_sizes, int n_in,
                              void* d_out, int out_size) {
    const float* x     = (const float*)d_in[0];
    const float* ln1_g = (const float*)d_in[1];
    const float* ln1_b = (const float*)d_in[2];
    const float* Wz    = (const float*)d_in[3];
    const float* bz    = (const float*)d_in[4];
    const float* Wh    = (const float*)d_in[5];
    const float* bh    = (const float*)d_in[6];
    const float* ln2_g = (const float*)d_in[7];
    const float* ln2_b = (const float*)d_in[8];
    const float* W1    = (const float*)d_in[9];
    const float* b1    = (const float*)d_in[10];
    const float* W2    = (const float*)d_in[11];
    const float* b2    = (const float*)d_in[12];
    float* out = (float*)d_out;

    __half *pAh, *pH1, *pWzh, *pW1h, *pW2h, *pKH, *pX2;
    float *pBzh, *pAc, *pBc, *pHc;
    cudaGetSymbolAddress((void**)&pAh,  g_Ah);
    cudaGetSymbolAddress((void**)&pH1,  g_H1);
    cudaGetSymbolAddress((void**)&pWzh, g_Wzh);
    cudaGetSymbolAddress((void**)&pW1h, g_W1h);
    cudaGetSymbolAddress((void**)&pW2h, g_W2h);
    cudaGetSymbolAddress((void**)&pKH,  g_kh);
    cudaGetSymbolAddress((void**)&pX2,  g_x2);
    cudaGetSymbolAddress((void**)&pBzh, g_bzh);
    cudaGetSymbolAddress((void**)&pAc,  g_Ac);
    cudaGetSymbolAddress((void**)&pBc,  g_Bc);
    cudaGetSymbolAddress((void**)&pHc,  g_Hc);

    cudaFuncSetAttribute(mma_gemm<1>, cudaFuncAttributeMaxDynamicSharedMemorySize, SMEM_TOT);
    cudaFuncSetAttribute(mma_gemm<2>, cudaFuncAttributeMaxDynamicSharedMemorySize, SMEM_TOT);
    cudaFuncSetAttribute(mma_gemm<3>, cudaFuncAttributeMaxDynamicSharedMemorySize, SMEM_TOT);

    // weight prep (one launch) + fused bias
    transpose_half4<<<dim3(16, 16, 4), dim3(32, 32)>>>(
        Wz, Wh, W1, W2, pWzh, pW1h, pW2h);
    bias_cat<<<4, 256>>>(bz, bh, pBzh);

    // LN1 -> fp16
    ln_half<<<MDIM, 128>>>(x, ln1_g, ln1_b, pAh);
    // [k | hpre] = LN1(x) @ [Wz | Wh] + [bz | bh]  (stored fp16)
    mma_gemm<3><<<dim3(8, MDIM / 128), 256, SMEM_TOT>>>(
        pAh, pWzh, pBzh, nullptr, nullptr, pKH, 1024);
    // chunked linear scan (gates inline, half2, fast sigmoid, 8-token batches)
    scan_p1<<<dim3(NCH, BDIM), 256>>>((const __half2*)pKH, (float2*)pAc, (float2*)pBc);
    scan_p2<<<BDIM, 256>>>((const float2*)pAc, (const float2*)pBc, (float2*)pHc);
    scan_p3<<<dim3(NCH, BDIM), 256>>>((const __half2*)pKH, (const float2*)pHc,
                                      (const float2*)x, (__half2*)pX2);
    // LN2 (fp16 in) -> fp16
    ln_half_h<<<MDIM, 128>>>(pX2, ln2_g, ln2_b, pAh);
    // h1 = relu(LN2 @ W1 + b1) -> fp16
    mma_gemm<1><<<dim3(4, MDIM / 128), 256, SMEM_TOT>>>(
        pAh, pW1h, b1, nullptr, nullptr, pH1, 512);
    // out = x2 + h1 @ W2 + b2   (fp16 residual, fp32 out)
    mma_gemm<2><<<dim3(4, MDIM / 128), 256, SMEM_TOT>>>(
        pH1, pW2h, b2, pX2, out, nullptr, 512);
}